// round 6
// baseline (speedup 1.0000x reference)
#include <cuda_runtime.h>
#include <math.h>

// ---------------------------------------------------------------------------
// PCGNN R6: R5 + shfl-based rank select (no sdiff smem) +
// Phase-D 2-e-columns-per-thread (halves broadcast LDS wavefronts).
// 512 thr, NB=16, 2 CTAs/SM, persistent regs = 40 (wreg32 + acc8).
// Shapes: N_SRC=60000, N_DST=30000, DEG=32, F=128, E=64, C=2, K=16
// ---------------------------------------------------------------------------

#define F_DIM   128
#define E_DIM   64
#define DEG     32
#define KSEL    16
#define NB      16         // nodes per block-iteration
#define ST      20         // staging stride (floats): 16B-aligned, 4-way conflicts
#define THREADS 512
#define NSL     16         // f-slices in Phase D (8 ff each)

#define N_SRC_MAX 60000
__device__ float g_sig[N_SRC_MAX];   // sigmoid(x[v]·Wd0 + b0) for every source row

// ---- score precompute: one warp per source row --------------------------------
__global__ void score_kernel(const float* __restrict__ x,
                             const float* __restrict__ Wd,   // [128,2] row-major
                             const float* __restrict__ bd,   // [2]
                             float* __restrict__ score_out,  // [n_dst,2]
                             int n_src, int n_dst) {
    int w    = (blockIdx.x * blockDim.x + threadIdx.x) >> 5;
    int lane = threadIdx.x & 31;
    if (w >= n_src) return;
    int f0 = lane * 4;
    float4 xv = *(const float4*)(x + (size_t)w * F_DIM + f0);
    float4 wA = *(const float4*)(Wd + f0 * 2);
    float4 wB = *(const float4*)(Wd + f0 * 2 + 4);
    float d0 = xv.x*wA.x + xv.y*wA.z + xv.z*wB.x + xv.w*wB.z;
    float d1 = xv.x*wA.y + xv.y*wA.w + xv.z*wB.y + xv.w*wB.w;
    #pragma unroll
    for (int o = 16; o; o >>= 1) {
        d0 += __shfl_xor_sync(0xffffffffu, d0, o);
        d1 += __shfl_xor_sync(0xffffffffu, d1, o);
    }
    if (lane == 0) {
        float s0 = d0 + bd[0];
        g_sig[w] = 1.0f / (1.0f + expf(-s0));
        if (w < n_dst) {
            score_out[(size_t)w * 2]     = s0;
            score_out[(size_t)w * 2 + 1] = d1 + bd[1];
        }
    }
}

// ---- dynamic SMEM layout (bytes), all 16B-aligned -----------------------------
#define SM_WO    0          // float2[64]      W_out rows                    512
#define SM_BS    512        // float [64]      b_sage                        256
#define SM_XD    768        // float [128*ST]  x_dst  [f][node]            10240
#define SM_HN    11008      // float [128*ST]  h_neigh [f][node]           10240
#define SM_PART  21248      // float [16*16*64] partials [sl][n][e]        65536
#define SM_H     86784      // float [16*64]   relu(h) [n][e]               4096
#define SM_SEL   90880      // int   [16*16]   selected neighbor ids        1024
#define SM_TOTAL 91904

__global__ __launch_bounds__(THREADS, 2)
void pcgnn_main_kernel(const float* __restrict__ x,
                       const int*   __restrict__ neighbors,
                       const float* __restrict__ W_self,   // [128,64]
                       const float* __restrict__ W_neigh,  // [128,64]
                       const float* __restrict__ b_sage,   // [64]
                       const float* __restrict__ W_out,    // [64,2]
                       const float* __restrict__ b_out,    // [2]
                       float* __restrict__ out_logits,     // [n_dst,2]
                       int n_dst) {
    extern __shared__ char sm[];
    float2* sWo   = (float2*)(sm + SM_WO);
    float*  sbs   = (float*) (sm + SM_BS);
    float*  sxd   = (float*) (sm + SM_XD);
    float*  shn   = (float*) (sm + SM_HN);
    float*  spart = (float*) (sm + SM_PART);
    float*  sh    = (float*) (sm + SM_H);
    int*    ssel  = (int*)   (sm + SM_SEL);

    const int tid  = threadIdx.x;
    const int g    = tid >> 5;        // warp 0..15
    const int lane = tid & 31;
    const int ep   = tid & 31;        // e-pair base: e in {ep, ep+32}  (Phase D)
    const int sl   = tid >> 5;        // f-slice 0..15 (= warp id)      (Phase D)
    const int f    = tid & 127;       // feature (gather)
    const int slot = tid >> 7;        // 0..3 (gather)

    // ---- loop-invariant weights: 8 ff x (Ws,Wn) x {ep, ep+32} = 32 regs ----
    float4 wreg[8];
    #pragma unroll
    for (int ff = 0; ff < 8; ff++) {
        const int fr = sl * 8 + ff;
        wreg[ff] = make_float4(W_self [fr * E_DIM + ep],
                               W_neigh[fr * E_DIM + ep],
                               W_self [fr * E_DIM + ep + 32],
                               W_neigh[fr * E_DIM + ep + 32]);
    }
    if (tid < E_DIM) {
        sWo[tid] = make_float2(W_out[tid * 2], W_out[tid * 2 + 1]);
        sbs[tid] = b_sage[tid];
    }
    const float bo0 = b_out[0], bo1 = b_out[1];

    for (int base = blockIdx.x * NB; base < n_dst; base += gridDim.x * NB) {
        // ---- Phase A: select via shfl rank — warp g, node base+g ----
        {
            const int node = base + g;
            if (node < n_dst) {
                int nb = neighbors[(size_t)node * DEG + lane];
                float t = g_sig[node];
                float d = fabsf(t - g_sig[nb]);
                int rank = 0;
                #pragma unroll
                for (int j = 0; j < 32; j++) {
                    float dj = __shfl_sync(0xffffffffu, d, j);
                    rank += (dj < d) || (dj == d && j < lane);
                }
                if (rank < KSEL) ssel[g * KSEL + rank] = nb;
            } else if (lane < KSEL) {
                ssel[g * KSEL + lane] = 0;   // safe dummy
            }
        }
        __syncthreads();

        // ---- Phase C: gather means + x_dst, thread = (f, slot of 4 nodes) ----
        {
            #pragma unroll
            for (int np = 0; np < 4; np++) {
                const int gg = np * 4 + slot;
                int nd = base + gg;
                if (nd >= n_dst) nd = n_dst - 1;
                float xdv = x[(size_t)nd * F_DIM + f];
                const int4* sp = (const int4*)(ssel + gg * KSEL);
                int4 iA = sp[0], iB = sp[1], iC = sp[2], iD = sp[3];
                float s0, s1, s2, s3;
                s0  = x[(size_t)iA.x * F_DIM + f];
                s1  = x[(size_t)iA.y * F_DIM + f];
                s2  = x[(size_t)iA.z * F_DIM + f];
                s3  = x[(size_t)iA.w * F_DIM + f];
                s0 += x[(size_t)iB.x * F_DIM + f];
                s1 += x[(size_t)iB.y * F_DIM + f];
                s2 += x[(size_t)iB.z * F_DIM + f];
                s3 += x[(size_t)iB.w * F_DIM + f];
                s0 += x[(size_t)iC.x * F_DIM + f];
                s1 += x[(size_t)iC.y * F_DIM + f];
                s2 += x[(size_t)iC.z * F_DIM + f];
                s3 += x[(size_t)iC.w * F_DIM + f];
                s0 += x[(size_t)iD.x * F_DIM + f];
                s1 += x[(size_t)iD.y * F_DIM + f];
                s2 += x[(size_t)iD.z * F_DIM + f];
                s3 += x[(size_t)iD.w * F_DIM + f];
                shn[f * ST + gg] = ((s0 + s1) + (s2 + s3)) * 0.0625f;
                sxd[f * ST + gg] = xdv;
            }
        }
        __syncthreads();

        // ---- Phase D: dual-GEMM; thread = (ep, sl); 4 node-quad passes ----
        // per ff: 2 broadcast LDS.128 feed 16 FFMA (2x the R5 ratio)
        #pragma unroll
        for (int q4 = 0; q4 < NB; q4 += 4) {
            float accA[4];   // e = ep
            float accB[4];   // e = ep + 32
            #pragma unroll
            for (int n = 0; n < 4; n++) { accA[n] = 0.f; accB[n] = 0.f; }
            #pragma unroll
            for (int ff = 0; ff < 8; ff++) {
                const int fr = sl * 8 + ff;
                float4 w  = wreg[ff];
                float4 xa = *(const float4*)(sxd + fr * ST + q4);
                float4 hb = *(const float4*)(shn + fr * ST + q4);
                accA[0] = fmaf(xa.x, w.x, fmaf(hb.x, w.y, accA[0]));
                accA[1] = fmaf(xa.y, w.x, fmaf(hb.y, w.y, accA[1]));
                accA[2] = fmaf(xa.z, w.x, fmaf(hb.z, w.y, accA[2]));
                accA[3] = fmaf(xa.w, w.x, fmaf(hb.w, w.y, accA[3]));
                accB[0] = fmaf(xa.x, w.z, fmaf(hb.x, w.w, accB[0]));
                accB[1] = fmaf(xa.y, w.z, fmaf(hb.y, w.w, accB[1]));
                accB[2] = fmaf(xa.z, w.z, fmaf(hb.z, w.w, accB[2]));
                accB[3] = fmaf(xa.w, w.z, fmaf(hb.w, w.w, accB[3]));
            }
            #pragma unroll
            for (int n = 0; n < 4; n++) {
                spart[(sl * NB + q4 + n) * E_DIM + ep]      = accA[n];
                spart[(sl * NB + q4 + n) * E_DIM + ep + 32] = accB[n];
            }
        }
        __syncthreads();

        // ---- reduce slices + bias + relu (1024 outputs, 2 per thread) ----
        #pragma unroll
        for (int r = 0; r < 2; r++) {
            const int p  = tid + r * THREADS;
            const int n  = p >> 6, ee = p & 63;
            float a0 = spart[(0  * NB + n) * E_DIM + ee]
                     + spart[(1  * NB + n) * E_DIM + ee];
            float a1 = spart[(2  * NB + n) * E_DIM + ee]
                     + spart[(3  * NB + n) * E_DIM + ee];
            float a2 = spart[(4  * NB + n) * E_DIM + ee]
                     + spart[(5  * NB + n) * E_DIM + ee];
            float a3 = spart[(6  * NB + n) * E_DIM + ee]
                     + spart[(7  * NB + n) * E_DIM + ee];
            float a4 = spart[(8  * NB + n) * E_DIM + ee]
                     + spart[(9  * NB + n) * E_DIM + ee];
            float a5 = spart[(10 * NB + n) * E_DIM + ee]
                     + spart[(11 * NB + n) * E_DIM + ee];
            float a6 = spart[(12 * NB + n) * E_DIM + ee]
                     + spart[(13 * NB + n) * E_DIM + ee];
            float a7 = spart[(14 * NB + n) * E_DIM + ee]
                     + spart[(15 * NB + n) * E_DIM + ee];
            float s = (((a0 + a1) + (a2 + a3)) + ((a4 + a5) + (a6 + a7))) + sbs[ee];
            sh[n * E_DIM + ee] = fmaxf(s, 0.f);
        }
        __syncthreads();

        // ---- Phase E: output projection, warp g -> node base+g ----
        {
            const int node = base + g;
            float h0 = sh[g * E_DIM + lane];
            float h1 = sh[g * E_DIM + 32 + lane];
            float2 w0 = sWo[lane];
            float2 w1 = sWo[lane + 32];
            float c0 = h0 * w0.x + h1 * w1.x;
            float c1 = h0 * w0.y + h1 * w1.y;
            #pragma unroll
            for (int o = 16; o; o >>= 1) {
                c0 += __shfl_xor_sync(0xffffffffu, c0, o);
                c1 += __shfl_xor_sync(0xffffffffu, c1, o);
            }
            if (lane == 0 && node < n_dst) {
                out_logits[(size_t)node * 2]     = c0 + bo0;
                out_logits[(size_t)node * 2 + 1] = c1 + bo1;
            }
        }
        // no trailing barrier: next A writes ssel (last read in C, 2 barriers
        // back); sh readers (E) vs next writers (reduce) are 3 barriers apart.
    }
}

extern "C" void kernel_launch(void* const* d_in, const int* in_sizes, int n_in,
                              void* d_out, int out_size) {
    const float* x        = (const float*)d_in[0];
    const int*   neighbors= (const int*)  d_in[1];
    const float* W_dist   = (const float*)d_in[2];
    const float* b_dist   = (const float*)d_in[3];
    const float* W_self   = (const float*)d_in[4];
    const float* W_neigh  = (const float*)d_in[5];
    const float* b_sage   = (const float*)d_in[6];
    const float* W_out    = (const float*)d_in[7];
    const float* b_out    = (const float*)d_in[8];

    const int n_src = in_sizes[0] / F_DIM;
    const int n_dst = in_sizes[1] / DEG;

    float* out    = (float*)d_out;
    float* logits = out;                     // [n_dst, 2]
    float* score  = out + (size_t)n_dst * 2; // [n_dst, 2]

    int blocks1 = (n_src + 7) / 8;
    score_kernel<<<blocks1, 256>>>(x, W_dist, b_dist, score, n_src, n_dst);

    cudaFuncSetAttribute(pcgnn_main_kernel,
                         cudaFuncAttributeMaxDynamicSharedMemorySize, SM_TOTAL);
    pcgnn_main_kernel<<<296, THREADS, SM_TOTAL>>>(
        x, neighbors, W_self, W_neigh, b_sage, W_out, b_out, logits, n_dst);
}

// round 7
// speedup vs baseline: 1.0333x; 1.0333x over previous
#include <cuda_runtime.h>
#include <math.h>

// ---------------------------------------------------------------------------
// PCGNN R7: f-paired fma.rn.f32x2 Phase D (FFMA2), node-major staging
// (conflict-free C stores + zero-pack f32x2 loads via ld.shared.v2.u64).
// 512 thr, NB=16, 2 CTAs/SM, persistent regs = 32 (wreg) + transients.
// Shapes: N_SRC=60000, N_DST=30000, DEG=32, F=128, E=64, C=2, K=16
// ---------------------------------------------------------------------------

#define F_DIM   128
#define E_DIM   64
#define DEG     32
#define KSEL    16
#define NB      16         // nodes per block-iteration
#define THREADS 512

#define N_SRC_MAX 60000
__device__ float g_sig[N_SRC_MAX];   // sigmoid(x[v]·Wd0 + b0) for every source row

#define FMA2(d, a, b, c) \
    asm("fma.rn.f32x2 %0, %1, %2, %3;" : "=l"(d) : "l"(a), "l"(b), "l"(c))
#define LDS_V2U64(a, b, addr) \
    asm volatile("ld.shared.v2.u64 {%0, %1}, [%2];" : "=l"(a), "=l"(b) : "r"(addr))
#define PACKF2(o, lo, hi) \
    asm("mov.b64 %0, {%1, %2};" : "=l"(o) : "f"(lo), "f"(hi))
#define UNPACKF2(lo, hi, v) \
    asm("mov.b64 {%0, %1}, %2;" : "=f"(lo), "=f"(hi) : "l"(v))

// ---- score precompute: one warp per source row --------------------------------
__global__ void score_kernel(const float* __restrict__ x,
                             const float* __restrict__ Wd,   // [128,2] row-major
                             const float* __restrict__ bd,   // [2]
                             float* __restrict__ score_out,  // [n_dst,2]
                             int n_src, int n_dst) {
    int w    = (blockIdx.x * blockDim.x + threadIdx.x) >> 5;
    int lane = threadIdx.x & 31;
    if (w >= n_src) return;
    int f0 = lane * 4;
    float4 xv = *(const float4*)(x + (size_t)w * F_DIM + f0);
    float4 wA = *(const float4*)(Wd + f0 * 2);
    float4 wB = *(const float4*)(Wd + f0 * 2 + 4);
    float d0 = xv.x*wA.x + xv.y*wA.z + xv.z*wB.x + xv.w*wB.z;
    float d1 = xv.x*wA.y + xv.y*wA.w + xv.z*wB.y + xv.w*wB.w;
    #pragma unroll
    for (int o = 16; o; o >>= 1) {
        d0 += __shfl_xor_sync(0xffffffffu, d0, o);
        d1 += __shfl_xor_sync(0xffffffffu, d1, o);
    }
    if (lane == 0) {
        float s0 = d0 + bd[0];
        g_sig[w] = 1.0f / (1.0f + expf(-s0));
        if (w < n_dst) {
            score_out[(size_t)w * 2]     = s0;
            score_out[(size_t)w * 2 + 1] = d1 + bd[1];
        }
    }
}

// ---- dynamic SMEM layout (bytes), all 16B-aligned -----------------------------
#define SM_WO    0          // float2[64]        W_out rows                  512
#define SM_BS    512        // float [64]        b_sage                      256
#define SM_XD    768        // float [16*128]    x_dst  [node][f]           8192
#define SM_HN    8960       // float [16*128]    h_neigh [node][f]          8192
#define SM_PART  17152      // float [16*16*64]  partials [sl][n][e]       65536
#define SM_H     82688      // float [16*64]     relu(h) [n][e]             4096
#define SM_SEL   86784      // int   [16*16]     selected neighbor ids      1024
#define SM_TOTAL 87808

__global__ __launch_bounds__(THREADS, 2)
void pcgnn_main_kernel(const float* __restrict__ x,
                       const int*   __restrict__ neighbors,
                       const float* __restrict__ W_self,   // [128,64]
                       const float* __restrict__ W_neigh,  // [128,64]
                       const float* __restrict__ b_sage,   // [64]
                       const float* __restrict__ W_out,    // [64,2]
                       const float* __restrict__ b_out,    // [2]
                       float* __restrict__ out_logits,     // [n_dst,2]
                       int n_dst) {
    extern __shared__ char sm[];
    float2* sWo   = (float2*)(sm + SM_WO);
    float*  sbs   = (float*) (sm + SM_BS);
    float*  sxd   = (float*) (sm + SM_XD);   // [node][f], stride 128
    float*  shn   = (float*) (sm + SM_HN);   // [node][f], stride 128
    float*  spart = (float*) (sm + SM_PART);
    float*  sh    = (float*) (sm + SM_H);
    int*    ssel  = (int*)   (sm + SM_SEL);

    const int tid  = threadIdx.x;
    const int g    = tid >> 5;        // warp 0..15
    const int lane = tid & 31;
    const int ep   = tid & 31;        // e-pair: e = {2ep, 2ep+1}   (Phase D)
    const int sl   = tid >> 5;        // f-slice 0..15 (8 f each)   (Phase D)
    const int f    = tid & 127;       // feature (gather)
    const int slot = tid >> 7;        // 0..3 (gather)

    // ---- loop-invariant weights, pre-packed as f32x2 over (evenf, oddf) ----
    // ws0/wn0 -> e=2ep ; ws1/wn1 -> e=2ep+1 ; k indexes f-pair sl*8+2k
    unsigned long long ws0[4], wn0[4], ws1[4], wn1[4];
    {
        const int e0 = 2 * ep, e1 = e0 + 1;
        #pragma unroll
        for (int k = 0; k < 4; k++) {
            const int fa = sl * 8 + 2 * k, fb = fa + 1;
            PACKF2(ws0[k], W_self [fa * E_DIM + e0], W_self [fb * E_DIM + e0]);
            PACKF2(wn0[k], W_neigh[fa * E_DIM + e0], W_neigh[fb * E_DIM + e0]);
            PACKF2(ws1[k], W_self [fa * E_DIM + e1], W_self [fb * E_DIM + e1]);
            PACKF2(wn1[k], W_neigh[fa * E_DIM + e1], W_neigh[fb * E_DIM + e1]);
        }
    }
    if (tid < E_DIM) {
        sWo[tid] = make_float2(W_out[tid * 2], W_out[tid * 2 + 1]);
        sbs[tid] = b_sage[tid];
    }
    const float bo0 = b_out[0], bo1 = b_out[1];

    // 32-bit shared addresses for Phase D vector loads
    const unsigned xbase = (unsigned)__cvta_generic_to_shared(sxd) + sl * 32;
    const unsigned hbase = (unsigned)__cvta_generic_to_shared(shn) + sl * 32;

    for (int base = blockIdx.x * NB; base < n_dst; base += gridDim.x * NB) {
        // ---- Phase A: select via shfl rank — warp g, node base+g ----
        {
            const int node = base + g;
            if (node < n_dst) {
                int nb = neighbors[(size_t)node * DEG + lane];
                float t = g_sig[node];
                float d = fabsf(t - g_sig[nb]);
                int rank = 0;
                #pragma unroll
                for (int j = 0; j < 32; j++) {
                    float dj = __shfl_sync(0xffffffffu, d, j);
                    rank += (dj < d) || (dj == d && j < lane);
                }
                if (rank < KSEL) ssel[g * KSEL + rank] = nb;
            } else if (lane < KSEL) {
                ssel[g * KSEL + lane] = 0;   // safe dummy
            }
        }
        __syncthreads();

        // ---- Phase C: gather means + x_dst -> [node][f] (conflict-free STS) ----
        {
            #pragma unroll
            for (int np = 0; np < 4; np++) {
                const int gg = np * 4 + slot;
                int nd = base + gg;
                if (nd >= n_dst) nd = n_dst - 1;
                float xdv = x[(size_t)nd * F_DIM + f];
                const int4* sp = (const int4*)(ssel + gg * KSEL);
                int4 iA = sp[0], iB = sp[1], iC = sp[2], iD = sp[3];
                float s0, s1, s2, s3;
                s0  = x[(size_t)iA.x * F_DIM + f];
                s1  = x[(size_t)iA.y * F_DIM + f];
                s2  = x[(size_t)iA.z * F_DIM + f];
                s3  = x[(size_t)iA.w * F_DIM + f];
                s0 += x[(size_t)iB.x * F_DIM + f];
                s1 += x[(size_t)iB.y * F_DIM + f];
                s2 += x[(size_t)iB.z * F_DIM + f];
                s3 += x[(size_t)iB.w * F_DIM + f];
                s0 += x[(size_t)iC.x * F_DIM + f];
                s1 += x[(size_t)iC.y * F_DIM + f];
                s2 += x[(size_t)iC.z * F_DIM + f];
                s3 += x[(size_t)iC.w * F_DIM + f];
                s0 += x[(size_t)iD.x * F_DIM + f];
                s1 += x[(size_t)iD.y * F_DIM + f];
                s2 += x[(size_t)iD.z * F_DIM + f];
                s3 += x[(size_t)iD.w * F_DIM + f];
                shn[gg * F_DIM + f] = ((s0 + s1) + (s2 + s3)) * 0.0625f;
                sxd[gg * F_DIM + f] = xdv;
            }
        }
        __syncthreads();

        // ---- Phase D: dual-GEMM with fma.rn.f32x2, f-paired ----
        // thread (ep, sl): e = {2ep, 2ep+1}, f = sl*8 .. sl*8+7
        {
            #pragma unroll 2
            for (int n = 0; n < NB; n++) {
                const unsigned xa = xbase + n * (F_DIM * 4);
                const unsigned ha = hbase + n * (F_DIM * 4);
                unsigned long long x0, x1, x2, x3, h0, h1, h2, h3;
                LDS_V2U64(x0, x1, xa);
                LDS_V2U64(x2, x3, xa + 16);
                LDS_V2U64(h0, h1, ha);
                LDS_V2U64(h2, h3, ha + 16);
                unsigned long long a0, a1;
                PACKF2(a0, 0.f, 0.f);
                PACKF2(a1, 0.f, 0.f);
                FMA2(a0, x0, ws0[0], a0);  FMA2(a1, x0, ws1[0], a1);
                FMA2(a0, x1, ws0[1], a0);  FMA2(a1, x1, ws1[1], a1);
                FMA2(a0, x2, ws0[2], a0);  FMA2(a1, x2, ws1[2], a1);
                FMA2(a0, x3, ws0[3], a0);  FMA2(a1, x3, ws1[3], a1);
                FMA2(a0, h0, wn0[0], a0);  FMA2(a1, h0, wn1[0], a1);
                FMA2(a0, h1, wn0[1], a0);  FMA2(a1, h1, wn1[1], a1);
                FMA2(a0, h2, wn0[2], a0);  FMA2(a1, h2, wn1[2], a1);
                FMA2(a0, h3, wn0[3], a0);  FMA2(a1, h3, wn1[3], a1);
                float lo, hi, p0, p1;
                UNPACKF2(lo, hi, a0);  p0 = lo + hi;   // e = 2ep
                UNPACKF2(lo, hi, a1);  p1 = lo + hi;   // e = 2ep+1
                *(float2*)(spart + (sl * NB + n) * E_DIM + 2 * ep) =
                    make_float2(p0, p1);
            }
        }
        __syncthreads();

        // ---- reduce slices + bias + relu (1024 outputs, 2 per thread) ----
        #pragma unroll
        for (int r = 0; r < 2; r++) {
            const int p  = tid + r * THREADS;
            const int n  = p >> 6, ee = p & 63;
            float a0 = spart[(0  * NB + n) * E_DIM + ee]
                     + spart[(1  * NB + n) * E_DIM + ee];
            float a1 = spart[(2  * NB + n) * E_DIM + ee]
                     + spart[(3  * NB + n) * E_DIM + ee];
            float a2 = spart[(4  * NB + n) * E_DIM + ee]
                     + spart[(5  * NB + n) * E_DIM + ee];
            float a3 = spart[(6  * NB + n) * E_DIM + ee]
                     + spart[(7  * NB + n) * E_DIM + ee];
            float a4 = spart[(8  * NB + n) * E_DIM + ee]
                     + spart[(9  * NB + n) * E_DIM + ee];
            float a5 = spart[(10 * NB + n) * E_DIM + ee]
                     + spart[(11 * NB + n) * E_DIM + ee];
            float a6 = spart[(12 * NB + n) * E_DIM + ee]
                     + spart[(13 * NB + n) * E_DIM + ee];
            float a7 = spart[(14 * NB + n) * E_DIM + ee]
                     + spart[(15 * NB + n) * E_DIM + ee];
            float s = (((a0 + a1) + (a2 + a3)) + ((a4 + a5) + (a6 + a7))) + sbs[ee];
            sh[n * E_DIM + ee] = fmaxf(s, 0.f);
        }
        __syncthreads();

        // ---- Phase E: output projection, warp g -> node base+g ----
        {
            const int node = base + g;
            float h0 = sh[g * E_DIM + lane];
            float h1 = sh[g * E_DIM + 32 + lane];
            float2 w0 = sWo[lane];
            float2 w1 = sWo[lane + 32];
            float c0 = h0 * w0.x + h1 * w1.x;
            float c1 = h0 * w0.y + h1 * w1.y;
            #pragma unroll
            for (int o = 16; o; o >>= 1) {
                c0 += __shfl_xor_sync(0xffffffffu, c0, o);
                c1 += __shfl_xor_sync(0xffffffffu, c1, o);
            }
            if (lane == 0 && node < n_dst) {
                out_logits[(size_t)node * 2]     = c0 + bo0;
                out_logits[(size_t)node * 2 + 1] = c1 + bo1;
            }
        }
        // no trailing barrier: next A writes ssel (last read in C, 2 barriers
        // back); sh readers (E) vs next writers (reduce) are 3 barriers apart.
    }
}

extern "C" void kernel_launch(void* const* d_in, const int* in_sizes, int n_in,
                              void* d_out, int out_size) {
    const float* x        = (const float*)d_in[0];
    const int*   neighbors= (const int*)  d_in[1];
    const float* W_dist   = (const float*)d_in[2];
    const float* b_dist   = (const float*)d_in[3];
    const float* W_self   = (const float*)d_in[4];
    const float* W_neigh  = (const float*)d_in[5];
    const float* b_sage   = (const float*)d_in[6];
    const float* W_out    = (const float*)d_in[7];
    const float* b_out    = (const float*)d_in[8];

    const int n_src = in_sizes[0] / F_DIM;
    const int n_dst = in_sizes[1] / DEG;

    float* out    = (float*)d_out;
    float* logits = out;                     // [n_dst, 2]
    float* score  = out + (size_t)n_dst * 2; // [n_dst, 2]

    int blocks1 = (n_src + 7) / 8;
    score_kernel<<<blocks1, 256>>>(x, W_dist, b_dist, score, n_src, n_dst);

    cudaFuncSetAttribute(pcgnn_main_kernel,
                         cudaFuncAttributeMaxDynamicSharedMemorySize, SM_TOTAL);
    pcgnn_main_kernel<<<296, THREADS, SM_TOTAL>>>(
        x, neighbors, W_self, W_neigh, b_sage, W_out, b_out, logits, n_dst);
}

// round 9
// speedup vs baseline: 1.0608x; 1.0266x over previous
#include <cuda_runtime.h>
#include <math.h>

// ---------------------------------------------------------------------------
// PCGNN R9 (= R8 re-bench after infra failure; Phase-D loop fully unrolled):
// warp-local fused select+gather and reduce+output. 2 barriers/iteration.
// FFMA2 Phase D. 512 thr, NB=16, 2 CTAs/SM.
// Shapes: N_SRC=60000, N_DST=30000, DEG=32, F=128, E=64, C=2, K=16
// ---------------------------------------------------------------------------

#define F_DIM   128
#define E_DIM   64
#define DEG     32
#define KSEL    16
#define NB      16         // nodes per block-iteration (= warps)
#define THREADS 512

#define N_SRC_MAX 60000
__device__ float g_sig[N_SRC_MAX];   // sigmoid(x[v]·Wd0 + b0) for every source row

#define FMA2(d, a, b, c) \
    asm("fma.rn.f32x2 %0, %1, %2, %3;" : "=l"(d) : "l"(a), "l"(b), "l"(c))
#define LDS_V2U64(a, b, addr) \
    asm volatile("ld.shared.v2.u64 {%0, %1}, [%2];" : "=l"(a), "=l"(b) : "r"(addr))
#define PACKF2(o, lo, hi) \
    asm("mov.b64 %0, {%1, %2};" : "=l"(o) : "f"(lo), "f"(hi))
#define UNPACKF2(lo, hi, v) \
    asm("mov.b64 {%0, %1}, %2;" : "=f"(lo), "=f"(hi) : "l"(v))

// ---- score precompute: one warp per source row --------------------------------
__global__ void score_kernel(const float* __restrict__ x,
                             const float* __restrict__ Wd,   // [128,2] row-major
                             const float* __restrict__ bd,   // [2]
                             float* __restrict__ score_out,  // [n_dst,2]
                             int n_src, int n_dst) {
    int w    = (blockIdx.x * blockDim.x + threadIdx.x) >> 5;
    int lane = threadIdx.x & 31;
    if (w >= n_src) return;
    int f0 = lane * 4;
    float4 xv = *(const float4*)(x + (size_t)w * F_DIM + f0);
    float4 wA = *(const float4*)(Wd + f0 * 2);
    float4 wB = *(const float4*)(Wd + f0 * 2 + 4);
    float d0 = xv.x*wA.x + xv.y*wA.z + xv.z*wB.x + xv.w*wB.z;
    float d1 = xv.x*wA.y + xv.y*wA.w + xv.z*wB.y + xv.w*wB.w;
    #pragma unroll
    for (int o = 16; o; o >>= 1) {
        d0 += __shfl_xor_sync(0xffffffffu, d0, o);
        d1 += __shfl_xor_sync(0xffffffffu, d1, o);
    }
    if (lane == 0) {
        float s0 = d0 + bd[0];
        g_sig[w] = 1.0f / (1.0f + expf(-s0));
        if (w < n_dst) {
            score_out[(size_t)w * 2]     = s0;
            score_out[(size_t)w * 2 + 1] = d1 + bd[1];
        }
    }
}

// ---- dynamic SMEM layout (bytes), all 16B-aligned -----------------------------
#define SM_XD    0          // float [16*128]    x_dst  [node][f]           8192
#define SM_HN    8192       // float [16*128]    h_neigh [node][f]          8192
#define SM_PART  16384      // float [16*16*64]  partials [sl][n][e]       65536
#define SM_SEL   81920      // int   [16*16]     selected neighbor ids      1024
#define SM_TOTAL 82944

__global__ __launch_bounds__(THREADS, 2)
void pcgnn_main_kernel(const float* __restrict__ x,
                       const int*   __restrict__ neighbors,
                       const float* __restrict__ W_self,   // [128,64]
                       const float* __restrict__ W_neigh,  // [128,64]
                       const float* __restrict__ b_sage,   // [64]
                       const float* __restrict__ W_out,    // [64,2]
                       const float* __restrict__ b_out,    // [2]
                       float* __restrict__ out_logits,     // [n_dst,2]
                       int n_dst) {
    extern __shared__ char sm[];
    float*  sxd   = (float*) (sm + SM_XD);   // [node][f], stride 128
    float*  shn   = (float*) (sm + SM_HN);   // [node][f], stride 128
    float*  spart = (float*) (sm + SM_PART);
    int*    ssel  = (int*)   (sm + SM_SEL);

    const int tid  = threadIdx.x;
    const int g    = tid >> 5;        // warp 0..15 (node slot / f-slice)
    const int lane = tid & 31;
    const int ep   = tid & 31;        // e-pair: e = {2ep, 2ep+1}   (Phase D)
    const int sl   = tid >> 5;        // f-slice 0..15 (8 f each)   (Phase D)

    // ---- loop-invariant weights, pre-packed as f32x2 over (evenf, oddf) ----
    unsigned long long ws0[4], wn0[4], ws1[4], wn1[4];
    {
        const int e0 = 2 * ep, e1 = e0 + 1;
        #pragma unroll
        for (int k = 0; k < 4; k++) {
            const int fa = sl * 8 + 2 * k, fb = fa + 1;
            PACKF2(ws0[k], W_self [fa * E_DIM + e0], W_self [fb * E_DIM + e0]);
            PACKF2(wn0[k], W_neigh[fa * E_DIM + e0], W_neigh[fb * E_DIM + e0]);
            PACKF2(ws1[k], W_self [fa * E_DIM + e1], W_self [fb * E_DIM + e1]);
            PACKF2(wn1[k], W_neigh[fa * E_DIM + e1], W_neigh[fb * E_DIM + e1]);
        }
    }
    // ---- loop-invariant reduce/output constants (registers) ----
    const float sbs0 = b_sage[lane];
    const float sbs1 = b_sage[lane + 32];
    const float2 wo0 = make_float2(W_out[lane * 2],        W_out[lane * 2 + 1]);
    const float2 wo1 = make_float2(W_out[(lane + 32) * 2], W_out[(lane + 32) * 2 + 1]);
    const float bo0 = b_out[0], bo1 = b_out[1];

    // 32-bit shared addresses for Phase D vector loads
    const unsigned xbase = (unsigned)__cvta_generic_to_shared(sxd) + sl * 32;
    const unsigned hbase = (unsigned)__cvta_generic_to_shared(shn) + sl * 32;

    for (int base = blockIdx.x * NB; base < n_dst; base += gridDim.x * NB) {
        const int nodeg  = base + g;
        const int node   = (nodeg < n_dst) ? nodeg : (n_dst - 1);   // clamped

        // ---- Phase A+C (warp-local): select then gather for node ----
        {
            // select: top-16 smallest |sig(node) - sig(nb)| via shfl rank
            int nb = neighbors[(size_t)node * DEG + lane];
            float t = g_sig[node];
            float d = fabsf(t - g_sig[nb]);
            int rank = 0;
            #pragma unroll
            for (int j = 0; j < 32; j++) {
                float dj = __shfl_sync(0xffffffffu, d, j);
                rank += (dj < d) || (dj == d && j < lane);
            }
            if (rank < KSEL) ssel[g * KSEL + rank] = nb;
            __syncwarp();

            // gather: lane covers f = lane + 32*j, j=0..3
            const int4* sp = (const int4*)(ssel + g * KSEL);
            int4 iA = sp[0], iB = sp[1], iC = sp[2], iD = sp[3];
            #pragma unroll
            for (int j = 0; j < 4; j++) {
                const int f = lane + 32 * j;
                float xdv = x[(size_t)node * F_DIM + f];
                float s0, s1, s2, s3;
                s0  = x[(size_t)iA.x * F_DIM + f];
                s1  = x[(size_t)iA.y * F_DIM + f];
                s2  = x[(size_t)iA.z * F_DIM + f];
                s3  = x[(size_t)iA.w * F_DIM + f];
                s0 += x[(size_t)iB.x * F_DIM + f];
                s1 += x[(size_t)iB.y * F_DIM + f];
                s2 += x[(size_t)iB.z * F_DIM + f];
                s3 += x[(size_t)iB.w * F_DIM + f];
                s0 += x[(size_t)iC.x * F_DIM + f];
                s1 += x[(size_t)iC.y * F_DIM + f];
                s2 += x[(size_t)iC.z * F_DIM + f];
                s3 += x[(size_t)iC.w * F_DIM + f];
                s0 += x[(size_t)iD.x * F_DIM + f];
                s1 += x[(size_t)iD.y * F_DIM + f];
                s2 += x[(size_t)iD.z * F_DIM + f];
                s3 += x[(size_t)iD.w * F_DIM + f];
                shn[g * F_DIM + f] = ((s0 + s1) + (s2 + s3)) * 0.0625f;
                sxd[g * F_DIM + f] = xdv;
            }
        }
        __syncthreads();   // all staging visible to all warps

        // ---- Phase D: dual-GEMM with fma.rn.f32x2, f-paired ----
        {
            #pragma unroll
            for (int n = 0; n < NB; n++) {
                const unsigned xa = xbase + n * (F_DIM * 4);
                const unsigned ha = hbase + n * (F_DIM * 4);
                unsigned long long x0, x1, x2, x3, h0, h1, h2, h3;
                LDS_V2U64(x0, x1, xa);
                LDS_V2U64(x2, x3, xa + 16);
                LDS_V2U64(h0, h1, ha);
                LDS_V2U64(h2, h3, ha + 16);
                unsigned long long a0, a1;
                PACKF2(a0, 0.f, 0.f);
                PACKF2(a1, 0.f, 0.f);
                FMA2(a0, x0, ws0[0], a0);  FMA2(a1, x0, ws1[0], a1);
                FMA2(a0, x1, ws0[1], a0);  FMA2(a1, x1, ws1[1], a1);
                FMA2(a0, x2, ws0[2], a0);  FMA2(a1, x2, ws1[2], a1);
                FMA2(a0, x3, ws0[3], a0);  FMA2(a1, x3, ws1[3], a1);
                FMA2(a0, h0, wn0[0], a0);  FMA2(a1, h0, wn1[0], a1);
                FMA2(a0, h1, wn0[1], a0);  FMA2(a1, h1, wn1[1], a1);
                FMA2(a0, h2, wn0[2], a0);  FMA2(a1, h2, wn1[2], a1);
                FMA2(a0, h3, wn0[3], a0);  FMA2(a1, h3, wn1[3], a1);
                float lo, hi, p0, p1;
                UNPACKF2(lo, hi, a0);  p0 = lo + hi;   // e = 2ep
                UNPACKF2(lo, hi, a1);  p1 = lo + hi;   // e = 2ep+1
                *(float2*)(spart + (sl * NB + n) * E_DIM + 2 * ep) =
                    make_float2(p0, p1);
            }
        }
        __syncthreads();   // spart complete

        // ---- Phase R+E (warp-local): reduce slices, bias+relu, project ----
        {
            float s0 = 0.f, s1 = 0.f;
            #pragma unroll
            for (int s = 0; s < NB; s++) {
                s0 += spart[(s * NB + g) * E_DIM + lane];
                s1 += spart[(s * NB + g) * E_DIM + lane + 32];
            }
            float h0 = fmaxf(s0 + sbs0, 0.f);
            float h1 = fmaxf(s1 + sbs1, 0.f);
            float c0 = h0 * wo0.x + h1 * wo1.x;
            float c1 = h0 * wo0.y + h1 * wo1.y;
            #pragma unroll
            for (int o = 16; o; o >>= 1) {
                c0 += __shfl_xor_sync(0xffffffffu, c0, o);
                c1 += __shfl_xor_sync(0xffffffffu, c1, o);
            }
            if (lane == 0 && nodeg < n_dst) {
                out_logits[(size_t)nodeg * 2]     = c0 + bo0;
                out_logits[(size_t)nodeg * 2 + 1] = c1 + bo1;
            }
        }
        // no trailing barrier:
        //  - next A+C writes sxd/shn/ssel; all D(i) reads of sxd/shn finished
        //    before the post-D barrier; ssel is warp-private (syncwarp-scoped).
        //  - next D writes spart only after the next pre-D barrier, which every
        //    warp reaches only after finishing its R+E spart reads.
    }
}

extern "C" void kernel_launch(void* const* d_in, const int* in_sizes, int n_in,
                              void* d_out, int out_size) {
    const float* x        = (const float*)d_in[0];
    const int*   neighbors= (const int*)  d_in[1];
    const float* W_dist   = (const float*)d_in[2];
    const float* b_dist   = (const float*)d_in[3];
    const float* W_self   = (const float*)d_in[4];
    const float* W_neigh  = (const float*)d_in[5];
    const float* b_sage   = (const float*)d_in[6];
    const float* W_out    = (const float*)d_in[7];
    const float* b_out    = (const float*)d_in[8];

    const int n_src = in_sizes[0] / F_DIM;
    const int n_dst = in_sizes[1] / DEG;

    float* out    = (float*)d_out;
    float* logits = out;                     // [n_dst, 2]
    float* score  = out + (size_t)n_dst * 2; // [n_dst, 2]

    int blocks1 = (n_src + 7) / 8;
    score_kernel<<<blocks1, 256>>>(x, W_dist, b_dist, score, n_src, n_dst);

    cudaFuncSetAttribute(pcgnn_main_kernel,
                         cudaFuncAttributeMaxDynamicSharedMemorySize, SM_TOTAL);
    pcgnn_main_kernel<<<296, THREADS, SM_TOTAL>>>(
        x, neighbors, W_self, W_neigh, b_sage, W_out, b_out, logits, n_dst);
}